// round 4
// baseline (speedup 1.0000x reference)
#include <cuda_runtime.h>
#include <cuda_bf16.h>
#include <math.h>

// Problem constants (fixed shapes from reference)
#define NROW   100000
#define IN_CH  128
#define OUT_CH 40
#define NED    3200000

// Scratch (static device globals; no allocation anywhere)
__device__ float4 g_y[NROW * 10];    // xW  (40 ch = 10 float4 per row), 16 MB
__device__ float4 g_h1[NROW * 10];   // after first propagation, 16 MB
__device__ float  g_dinv[NROW];
__device__ int    g_degi[NROW];
__device__ int2   g_edges[NED];      // (src,dst) pairs, 25.6 MB

// ---------------------------------------------------------------------------
// 1) deg init (self-loop contributes 1)
__global__ void k_deg_init() {
    int i = blockIdx.x * blockDim.x + threadIdx.x;
    if (i < NROW) g_degi[i] = 1;
}

// 2) decode int32 edge_index -> int2, count in-degree on col.
//    NOTE: edge_index is int32 (JAX default x64-disabled downcasts int64).
__global__ void k_edges(const int* __restrict__ ei) {
    int e = blockIdx.x * blockDim.x + threadIdx.x;
    if (e >= NED) return;
    int r = ei[e];
    int c = ei[NED + e];
    // defensive clamp: if dtype assumption is wrong we get rel_err, not a crash
    if ((unsigned)r >= NROW) r = 0;
    if ((unsigned)c >= NROW) c = 0;
    g_edges[e] = make_int2(r, c);
    atomicAdd(&g_degi[c], 1);
}

// 3) dinv = 1/sqrt(deg)
__global__ void k_dinv() {
    int i = blockIdx.x * blockDim.x + threadIdx.x;
    if (i < NROW) g_dinv[i] = rsqrtf((float)g_degi[i]);
}

// ---------------------------------------------------------------------------
// 4) GEMM: y = x @ W; also h1 = y * dinv^2 (self-loop term of first prop).
//    One thread: 2 rows x 20 channels (40 accumulators). W staged in smem.
__device__ __forceinline__ void fma4(float4& a, float s, float4 w) {
    a.x += s * w.x; a.y += s * w.y; a.z += s * w.z; a.w += s * w.w;
}

__global__ void k_gemm(const float* __restrict__ x, const float* __restrict__ W) {
    __shared__ __align__(16) float wsm[IN_CH * OUT_CH];   // 20 KB
    for (int i = threadIdx.x; i < IN_CH * OUT_CH; i += blockDim.x)
        wsm[i] = W[i];
    __syncthreads();

    int gid = blockIdx.x * blockDim.x + threadIdx.x;
    if (gid >= NROW) return;                 // NROW threads total
    int pair = gid >> 1;                     // row pair index
    int ch   = (gid & 1) * 20;               // channel half: 0 or 20
    int r0 = pair * 2, r1 = r0 + 1;

    float4 acc0[5], acc1[5];
    #pragma unroll
    for (int j = 0; j < 5; j++) {
        acc0[j] = make_float4(0.f, 0.f, 0.f, 0.f);
        acc1[j] = make_float4(0.f, 0.f, 0.f, 0.f);
    }

    const float4* x0 = (const float4*)(x + (size_t)r0 * IN_CH);
    const float4* x1 = (const float4*)(x + (size_t)r1 * IN_CH);

    for (int k4 = 0; k4 < IN_CH / 4; k4++) {
        float4 xa = __ldg(&x0[k4]);
        float4 xb = __ldg(&x1[k4]);
        const float* wrow = wsm + (k4 * 4) * OUT_CH + ch;
        #pragma unroll
        for (int kk = 0; kk < 4; kk++) {
            float a = (&xa.x)[kk];
            float b = (&xb.x)[kk];
            const float4* wv = (const float4*)(wrow + kk * OUT_CH);
            #pragma unroll
            for (int j = 0; j < 5; j++) {
                float4 w4 = wv[j];
                fma4(acc0[j], a, w4);
                fma4(acc1[j], b, w4);
            }
        }
    }

    float d0 = g_dinv[r0], d1 = g_dinv[r1];
    float s0 = d0 * d0, s1 = d1 * d1;
    int base0 = r0 * 10 + (ch >> 2);
    int base1 = r1 * 10 + (ch >> 2);
    #pragma unroll
    for (int j = 0; j < 5; j++) {
        g_y[base0 + j]  = acc0[j];
        g_y[base1 + j]  = acc1[j];
        g_h1[base0 + j] = make_float4(acc0[j].x * s0, acc0[j].y * s0,
                                      acc0[j].z * s0, acc0[j].w * s0);
        g_h1[base1 + j] = make_float4(acc1[j].x * s1, acc1[j].y * s1,
                                      acc1[j].z * s1, acc1[j].w * s1);
    }
}

// ---------------------------------------------------------------------------
// Edge scatter: dst[col] += dinv[row]*dinv[col] * src[row], vectorized reds.
__device__ __forceinline__ void red_add_v4(float4* p, float a, float b, float c, float d) {
    asm volatile("red.global.add.v4.f32 [%0], {%1, %2, %3, %4};"
                 :: "l"(p), "f"(a), "f"(b), "f"(c), "f"(d) : "memory");
}

__device__ __forceinline__ void prop_edge(int e, const float4* __restrict__ src,
                                          float4* dst) {
    int2 rc = g_edges[e];
    float w = g_dinv[rc.x] * g_dinv[rc.y];
    const float4* s = src + (size_t)rc.x * 10;
    float4* d = dst + (size_t)rc.y * 10;
    float4 v[10];
    #pragma unroll
    for (int j = 0; j < 10; j++) v[j] = __ldg(&s[j]);
    #pragma unroll
    for (int j = 0; j < 10; j++)
        red_add_v4(d + j, w * v[j].x, w * v[j].y, w * v[j].z, w * v[j].w);
}

// 5) pass 1: h1 += norm * y      (scratch globals bound directly)
__global__ void k_prop1() {
    int e = blockIdx.x * blockDim.x + threadIdx.x;
    if (e < NED) prop_edge(e, g_y, g_h1);
}

// 6) d_out = h1 * dinv^2 (self-loop term of pass 2; also un-poisons d_out)
__global__ void k_selfinit(float4* out) {
    int gid = blockIdx.x * blockDim.x + threadIdx.x;
    if (gid >= NROW * 10) return;
    int row = gid / 10;
    float d = g_dinv[row];
    float s = d * d;
    float4 v = g_h1[gid];
    out[gid] = make_float4(v.x * s, v.y * s, v.z * s, v.w * s);
}

// 7) pass 2: out += norm * h1
__global__ void k_prop2(float4* out) {
    int e = blockIdx.x * blockDim.x + threadIdx.x;
    if (e < NED) prop_edge(e, g_h1, out);
}

// ---------------------------------------------------------------------------
// 8) out = log_softmax(out + b), in place, one thread per row.
__global__ void k_logsoftmax(float* out, const float* __restrict__ bias) {
    int row = blockIdx.x * blockDim.x + threadIdx.x;
    if (row >= NROW) return;
    float v[OUT_CH];
    float4* o4 = (float4*)(out + (size_t)row * OUT_CH);
    #pragma unroll
    for (int j = 0; j < 10; j++) {
        float4 t = o4[j];
        v[4*j+0] = t.x + __ldg(&bias[4*j+0]);
        v[4*j+1] = t.y + __ldg(&bias[4*j+1]);
        v[4*j+2] = t.z + __ldg(&bias[4*j+2]);
        v[4*j+3] = t.w + __ldg(&bias[4*j+3]);
    }
    float m = v[0];
    #pragma unroll
    for (int c = 1; c < OUT_CH; c++) m = fmaxf(m, v[c]);
    float s = 0.f;
    #pragma unroll
    for (int c = 0; c < OUT_CH; c++) s += expf(v[c] - m);
    float l = m + logf(s);
    #pragma unroll
    for (int j = 0; j < 10; j++)
        o4[j] = make_float4(v[4*j+0] - l, v[4*j+1] - l,
                            v[4*j+2] - l, v[4*j+3] - l);
}

// ---------------------------------------------------------------------------
extern "C" void kernel_launch(void* const* d_in, const int* in_sizes, int n_in,
                              void* d_out, int out_size) {
    const float* x  = (const float*)d_in[0];
    const int*   ei = (const int*)d_in[1];     // int32 (JAX x64 disabled)
    const float* W  = (const float*)d_in[2];
    const float* b  = (const float*)d_in[3];
    float*       out = (float*)d_out;

    const int T = 256;
    const int gN  = (NROW + T - 1) / T;
    const int gE  = (NED + T - 1) / T;
    const int gNC = (NROW * 10 + T - 1) / T;

    k_deg_init<<<gN, T>>>();
    k_edges<<<gE, T>>>(ei);
    k_dinv<<<gN, T>>>();
    k_gemm<<<gN, T>>>(x, W);
    k_prop1<<<gE, T>>>();
    k_selfinit<<<gNC, T>>>((float4*)out);
    k_prop2<<<gE, T>>>((float4*)out);
    k_logsoftmax<<<gN, T>>>(out, b);
}

// round 5
// speedup vs baseline: 2.3454x; 2.3454x over previous
#include <cuda_runtime.h>
#include <cuda_bf16.h>
#include <math.h>

#define NROW   100000
#define IN_CH  128
#define OUT_CH 40
#define NED    3200000
#define NBLK   ((NROW + 255) / 256)   // 391 scan blocks

// Scratch (static device globals)
__device__ float4 g_y [NROW * 10];   // z0 = (xW)*dinv, then reused as needed (16 MB)
__device__ float4 g_h1[NROW * 10];   // z1 after hop 1 (16 MB)
__device__ float  g_dinv[NROW];
__device__ int    g_degi[NROW];      // in-degree incl. self-loop
__device__ int    g_start[NROW];     // CSC row starts (edges only, no self-loop)
__device__ int    g_cursor[NROW];    // fill cursors
__device__ int    g_srcs[NED];       // CSC source indices (12.8 MB)
__device__ int    g_bsum[NBLK];
__device__ int    g_boff[NBLK];

__device__ __forceinline__ void add4(float4& a, float4 b) {
    a.x += b.x; a.y += b.y; a.z += b.z; a.w += b.w;
}

// ---------------------------------------------------------------------------
__global__ void k_deg_init() {
    int i = blockIdx.x * blockDim.x + threadIdx.x;
    if (i < NROW) g_degi[i] = 1;                 // self-loop
}

// count in-degree (reads only the col half of edge_index; int32 per JAX default)
__global__ void k_count(const int* __restrict__ ei) {
    int e = blockIdx.x * blockDim.x + threadIdx.x;
    if (e >= NED) return;
    int c = ei[NED + e];
    if ((unsigned)c >= NROW) c = 0;
    atomicAdd(&g_degi[c], 1);
}

__global__ void k_dinv() {
    int i = blockIdx.x * blockDim.x + threadIdx.x;
    if (i < NROW) g_dinv[i] = rsqrtf((float)g_degi[i]);
}

// ---------------------------------------------------------------------------
// Two-level exclusive scan over edge counts (degi - 1)
__global__ void k_scan_nodes() {
    __shared__ int sh[256];
    int tid = threadIdx.x;
    int i = blockIdx.x * 256 + tid;
    int c = (i < NROW) ? (g_degi[i] - 1) : 0;
    sh[tid] = c;
    __syncthreads();
    #pragma unroll
    for (int off = 1; off < 256; off <<= 1) {
        int t = (tid >= off) ? sh[tid - off] : 0;
        __syncthreads();
        sh[tid] += t;
        __syncthreads();
    }
    if (i < NROW) g_start[i] = sh[tid] - c;      // exclusive within block
    if (tid == 255) g_bsum[blockIdx.x] = sh[tid];
}

__global__ void k_scan_tops() {
    __shared__ int sh[512];
    int tid = threadIdx.x;
    int v = (tid < NBLK) ? g_bsum[tid] : 0;
    sh[tid] = v;
    __syncthreads();
    #pragma unroll
    for (int off = 1; off < 512; off <<= 1) {
        int t = (tid >= off) ? sh[tid - off] : 0;
        __syncthreads();
        sh[tid] += t;
        __syncthreads();
    }
    if (tid < NBLK) g_boff[tid] = sh[tid] - v;   // exclusive block offsets
}

__global__ void k_finalize() {
    int i = blockIdx.x * blockDim.x + threadIdx.x;
    if (i >= NROW) return;
    int s = g_start[i] + g_boff[i >> 8];
    g_start[i] = s;
    g_cursor[i] = s;
}

// fill CSC: for each edge write its src into dst's slot
__global__ void k_fill(const int* __restrict__ ei) {
    int e = blockIdx.x * blockDim.x + threadIdx.x;
    if (e >= NED) return;
    int r = ei[e];
    int c = ei[NED + e];
    if ((unsigned)r >= NROW) r = 0;
    if ((unsigned)c >= NROW) c = 0;
    int slot = atomicAdd(&g_cursor[c], 1);
    g_srcs[slot] = r;
}

// ---------------------------------------------------------------------------
// GEMM: z0 = (x @ W) * dinv[row].  One thread: 2 rows x 20 channels.
__device__ __forceinline__ void fma4(float4& a, float s, float4 w) {
    a.x += s * w.x; a.y += s * w.y; a.z += s * w.z; a.w += s * w.w;
}

__global__ void k_gemm(const float* __restrict__ x, const float* __restrict__ W) {
    __shared__ __align__(16) float wsm[IN_CH * OUT_CH];
    for (int i = threadIdx.x; i < IN_CH * OUT_CH; i += blockDim.x)
        wsm[i] = W[i];
    __syncthreads();

    int gid = blockIdx.x * blockDim.x + threadIdx.x;
    if (gid >= NROW) return;
    int pair = gid >> 1;
    int ch   = (gid & 1) * 20;
    int r0 = pair * 2, r1 = r0 + 1;

    float4 acc0[5], acc1[5];
    #pragma unroll
    for (int j = 0; j < 5; j++) {
        acc0[j] = make_float4(0.f, 0.f, 0.f, 0.f);
        acc1[j] = make_float4(0.f, 0.f, 0.f, 0.f);
    }

    const float4* x0 = (const float4*)(x + (size_t)r0 * IN_CH);
    const float4* x1 = (const float4*)(x + (size_t)r1 * IN_CH);

    for (int k4 = 0; k4 < IN_CH / 4; k4++) {
        float4 xa = __ldg(&x0[k4]);
        float4 xb = __ldg(&x1[k4]);
        const float* wrow = wsm + (k4 * 4) * OUT_CH + ch;
        #pragma unroll
        for (int kk = 0; kk < 4; kk++) {
            float a = (&xa.x)[kk];
            float b = (&xb.x)[kk];
            const float4* wv = (const float4*)(wrow + kk * OUT_CH);
            #pragma unroll
            for (int j = 0; j < 5; j++) {
                float4 w4 = wv[j];
                fma4(acc0[j], a, w4);
                fma4(acc1[j], b, w4);
            }
        }
    }

    float d0 = g_dinv[r0], d1 = g_dinv[r1];
    int base0 = r0 * 10 + (ch >> 2);
    int base1 = r1 * 10 + (ch >> 2);
    #pragma unroll
    for (int j = 0; j < 5; j++) {
        g_y[base0 + j] = make_float4(acc0[j].x * d0, acc0[j].y * d0,
                                     acc0[j].z * d0, acc0[j].w * d0);
        g_y[base1 + j] = make_float4(acc1[j].x * d1, acc1[j].y * d1,
                                     acc1[j].z * d1, acc1[j].w * d1);
    }
}

// ---------------------------------------------------------------------------
// Gather hop: thread = (node, float4 chunk). 10 consecutive threads per node
// -> broadcast index loads, coalesced 160B row gathers. No atomics.
__device__ __forceinline__ float4 gather_row(int node, int ch,
                                             const float4* __restrict__ src) {
    float4 acc = src[node * 10 + ch];            // self term z[c]
    int s0  = g_start[node];
    int cnt = g_degi[node] - 1;
    float4 a1 = make_float4(0.f,0.f,0.f,0.f);
    float4 a2 = make_float4(0.f,0.f,0.f,0.f);
    float4 a3 = make_float4(0.f,0.f,0.f,0.f);
    int k = 0;
    for (; k + 4 <= cnt; k += 4) {
        int i0 = g_srcs[s0 + k + 0];
        int i1 = g_srcs[s0 + k + 1];
        int i2 = g_srcs[s0 + k + 2];
        int i3 = g_srcs[s0 + k + 3];
        float4 v0 = __ldg(&src[i0 * 10 + ch]);
        float4 v1 = __ldg(&src[i1 * 10 + ch]);
        float4 v2 = __ldg(&src[i2 * 10 + ch]);
        float4 v3 = __ldg(&src[i3 * 10 + ch]);
        add4(acc, v0); add4(a1, v1); add4(a2, v2); add4(a3, v3);
    }
    for (; k < cnt; k++) {
        int i0 = g_srcs[s0 + k];
        add4(acc, __ldg(&src[i0 * 10 + ch]));
    }
    add4(a1, a2); add4(acc, a3); add4(acc, a1);
    return acc;
}

// hop 1: z1 = dinv^2 * (z0[c] + sum z0[srcs])
__global__ void k_gather1() {
    int t = blockIdx.x * blockDim.x + threadIdx.x;
    if (t >= NROW * 10) return;
    int node = t / 10, ch = t % 10;
    float4 acc = gather_row(node, ch, g_y);
    float d = g_dinv[node];
    float s = d * d;
    g_h1[t] = make_float4(acc.x * s, acc.y * s, acc.z * s, acc.w * s);
}

// hop 2: out = dinv * (z1[c] + sum z1[srcs]) + b
__global__ void k_gather2(float4* out, const float* __restrict__ bias) {
    int t = blockIdx.x * blockDim.x + threadIdx.x;
    if (t >= NROW * 10) return;
    int node = t / 10, ch = t % 10;
    float4 acc = gather_row(node, ch, g_h1);
    float d = g_dinv[node];
    out[t] = make_float4(acc.x * d + __ldg(&bias[ch*4+0]),
                         acc.y * d + __ldg(&bias[ch*4+1]),
                         acc.z * d + __ldg(&bias[ch*4+2]),
                         acc.w * d + __ldg(&bias[ch*4+3]));
}

// ---------------------------------------------------------------------------
// log_softmax in place, one thread per row
__global__ void k_logsoftmax(float* out) {
    int row = blockIdx.x * blockDim.x + threadIdx.x;
    if (row >= NROW) return;
    float v[OUT_CH];
    float4* o4 = (float4*)(out + (size_t)row * OUT_CH);
    #pragma unroll
    for (int j = 0; j < 10; j++) {
        float4 tv = o4[j];
        v[4*j+0] = tv.x; v[4*j+1] = tv.y; v[4*j+2] = tv.z; v[4*j+3] = tv.w;
    }
    float m = v[0];
    #pragma unroll
    for (int c = 1; c < OUT_CH; c++) m = fmaxf(m, v[c]);
    float s = 0.f;
    #pragma unroll
    for (int c = 0; c < OUT_CH; c++) s += expf(v[c] - m);
    float l = m + logf(s);
    #pragma unroll
    for (int j = 0; j < 10; j++)
        o4[j] = make_float4(v[4*j+0] - l, v[4*j+1] - l,
                            v[4*j+2] - l, v[4*j+3] - l);
}

// ---------------------------------------------------------------------------
extern "C" void kernel_launch(void* const* d_in, const int* in_sizes, int n_in,
                              void* d_out, int out_size) {
    const float* x  = (const float*)d_in[0];
    const int*   ei = (const int*)d_in[1];
    const float* W  = (const float*)d_in[2];
    const float* b  = (const float*)d_in[3];
    float*       out = (float*)d_out;

    const int T = 256;
    const int gN  = (NROW + T - 1) / T;          // 391
    const int gE  = (NED + T - 1) / T;           // 12500
    const int gC  = (NROW * 10 + T - 1) / T;     // 3907

    k_deg_init  <<<gN, T>>>();
    k_count     <<<gE, T>>>(ei);
    k_dinv      <<<gN, T>>>();
    k_scan_nodes<<<NBLK, 256>>>();
    k_scan_tops <<<1, 512>>>();
    k_finalize  <<<gN, T>>>();
    k_fill      <<<gE, T>>>(ei);
    k_gemm      <<<gN, T>>>(x, W);
    k_gather1   <<<gC, T>>>();
    k_gather2   <<<gC, T>>>((float4*)out, b);
    k_logsoftmax<<<gN, T>>>(out);
}

// round 6
// speedup vs baseline: 2.7401x; 1.1683x over previous
#include <cuda_runtime.h>
#include <cuda_fp16.h>
#include <math.h>

#define NROW   100000
#define IN_CH  128
#define OUT_CH 40
#define NED    3200000
#define NBLK   ((NROW + 255) / 256)   // 391 scan blocks

// Scratch (static device globals)
__device__ __half2 g_z0[NROW * 20];  // (xW)*dinv, fp16, 80 B/row (8 MB)
__device__ __half2 g_z1[NROW * 20];  // after hop 1, fp16 (8 MB)
__device__ float   g_dinv[NROW];
__device__ int     g_degi[NROW];     // in-degree incl. self-loop
__device__ int     g_start[NROW];    // CSC row starts (edges only)
__device__ int     g_cursor[NROW];
__device__ int     g_srcs[NED];      // CSC source indices (12.8 MB)
__device__ int     g_bsum[NBLK];
__device__ int     g_boff[NBLK];

// ---------------------------------------------------------------------------
__global__ void k_deg_init() {
    int i = blockIdx.x * blockDim.x + threadIdx.x;
    if (i < NROW) g_degi[i] = 1;                 // self-loop
}

__global__ void k_count(const int* __restrict__ ei) {
    int e = blockIdx.x * blockDim.x + threadIdx.x;
    if (e >= NED) return;
    int c = ei[NED + e];
    if ((unsigned)c >= NROW) c = 0;
    atomicAdd(&g_degi[c], 1);
}

// ---------------------------------------------------------------------------
// Two-level exclusive scan over edge counts (degi - 1)
__global__ void k_scan_nodes() {
    __shared__ int sh[256];
    int tid = threadIdx.x;
    int i = blockIdx.x * 256 + tid;
    int c = (i < NROW) ? (g_degi[i] - 1) : 0;
    sh[tid] = c;
    __syncthreads();
    #pragma unroll
    for (int off = 1; off < 256; off <<= 1) {
        int t = (tid >= off) ? sh[tid - off] : 0;
        __syncthreads();
        sh[tid] += t;
        __syncthreads();
    }
    if (i < NROW) g_start[i] = sh[tid] - c;
    if (tid == 255) g_bsum[blockIdx.x] = sh[tid];
}

__global__ void k_scan_tops() {
    __shared__ int sh[512];
    int tid = threadIdx.x;
    int v = (tid < NBLK) ? g_bsum[tid] : 0;
    sh[tid] = v;
    __syncthreads();
    #pragma unroll
    for (int off = 1; off < 512; off <<= 1) {
        int t = (tid >= off) ? sh[tid - off] : 0;
        __syncthreads();
        sh[tid] += t;
        __syncthreads();
    }
    if (tid < NBLK) g_boff[tid] = sh[tid] - v;
}

// finalize offsets + compute dinv (fused)
__global__ void k_finalize() {
    int i = blockIdx.x * blockDim.x + threadIdx.x;
    if (i >= NROW) return;
    int s = g_start[i] + g_boff[i >> 8];
    g_start[i] = s;
    g_cursor[i] = s;
    g_dinv[i] = rsqrtf((float)g_degi[i]);
}

__global__ void k_fill(const int* __restrict__ ei) {
    int e = blockIdx.x * blockDim.x + threadIdx.x;
    if (e >= NED) return;
    int r = ei[e];
    int c = ei[NED + e];
    if ((unsigned)r >= NROW) r = 0;
    if ((unsigned)c >= NROW) c = 0;
    int slot = atomicAdd(&g_cursor[c], 1);
    g_srcs[slot] = r;
}

// ---------------------------------------------------------------------------
// GEMM: z0 = (x @ W) * dinv[row], stored fp16.  Thread: 2 rows x 20 channels.
__device__ __forceinline__ void fma4(float4& a, float s, float4 w) {
    a.x += s * w.x; a.y += s * w.y; a.z += s * w.z; a.w += s * w.w;
}

__global__ void k_gemm(const float* __restrict__ x, const float* __restrict__ W) {
    __shared__ __align__(16) float wsm[IN_CH * OUT_CH];
    for (int i = threadIdx.x; i < IN_CH * OUT_CH; i += blockDim.x)
        wsm[i] = W[i];
    __syncthreads();

    int gid = blockIdx.x * blockDim.x + threadIdx.x;
    if (gid >= NROW) return;
    int pair = gid >> 1;
    int ch   = (gid & 1) * 20;
    int r0 = pair * 2, r1 = r0 + 1;

    float4 acc0[5], acc1[5];
    #pragma unroll
    for (int j = 0; j < 5; j++) {
        acc0[j] = make_float4(0.f, 0.f, 0.f, 0.f);
        acc1[j] = make_float4(0.f, 0.f, 0.f, 0.f);
    }

    const float4* x0 = (const float4*)(x + (size_t)r0 * IN_CH);
    const float4* x1 = (const float4*)(x + (size_t)r1 * IN_CH);

    for (int k4 = 0; k4 < IN_CH / 4; k4++) {
        float4 xa = __ldg(&x0[k4]);
        float4 xb = __ldg(&x1[k4]);
        const float* wrow = wsm + (k4 * 4) * OUT_CH + ch;
        #pragma unroll
        for (int kk = 0; kk < 4; kk++) {
            float a = (&xa.x)[kk];
            float b = (&xb.x)[kk];
            const float4* wv = (const float4*)(wrow + kk * OUT_CH);
            #pragma unroll
            for (int j = 0; j < 5; j++) {
                float4 w4 = wv[j];
                fma4(acc0[j], a, w4);
                fma4(acc1[j], b, w4);
            }
        }
    }

    float d0 = g_dinv[r0], d1 = g_dinv[r1];
    __half2* z0 = g_z0 + r0 * 20 + (ch >> 1);
    __half2* z1 = g_z0 + r1 * 20 + (ch >> 1);
    #pragma unroll
    for (int j = 0; j < 5; j++) {
        z0[2*j]   = __floats2half2_rn(acc0[j].x * d0, acc0[j].y * d0);
        z0[2*j+1] = __floats2half2_rn(acc0[j].z * d0, acc0[j].w * d0);
        z1[2*j]   = __floats2half2_rn(acc1[j].x * d1, acc1[j].y * d1);
        z1[2*j+1] = __floats2half2_rn(acc1[j].z * d1, acc1[j].w * d1);
    }
}

// ---------------------------------------------------------------------------
// fp16 gather core: thread = (node, chunk c in 0..4), chunk = 8 channels
// (= 4 half2 = one uint4 load per gathered row). fp32 accumulators.
__device__ __forceinline__ void hacc(float* a, uint4 v) {
    float2 f;
    f = __half22float2(*(__half2*)&v.x); a[0] += f.x; a[1] += f.y;
    f = __half22float2(*(__half2*)&v.y); a[2] += f.x; a[3] += f.y;
    f = __half22float2(*(__half2*)&v.z); a[4] += f.x; a[5] += f.y;
    f = __half22float2(*(__half2*)&v.w); a[6] += f.x; a[7] += f.y;
}

__device__ __forceinline__ void gather8(float* acc, int node, int c,
                                        const __half2* __restrict__ src) {
    const uint4* base = (const uint4*)src;     // 5 uint4 per row
    #pragma unroll
    for (int j = 0; j < 8; j++) acc[j] = 0.f;
    float b[8];
    #pragma unroll
    for (int j = 0; j < 8; j++) b[j] = 0.f;

    uint4 self = __ldg(base + node * 5 + c);
    hacc(acc, self);

    int s0  = g_start[node];
    int cnt = g_degi[node] - 1;
    int k = 0;
    for (; k + 4 <= cnt; k += 4) {
        int i0 = g_srcs[s0 + k + 0];
        int i1 = g_srcs[s0 + k + 1];
        int i2 = g_srcs[s0 + k + 2];
        int i3 = g_srcs[s0 + k + 3];
        uint4 v0 = __ldg(base + i0 * 5 + c);
        uint4 v1 = __ldg(base + i1 * 5 + c);
        uint4 v2 = __ldg(base + i2 * 5 + c);
        uint4 v3 = __ldg(base + i3 * 5 + c);
        hacc(acc, v0); hacc(b, v1); hacc(acc, v2); hacc(b, v3);
    }
    for (; k < cnt; k++) {
        int i0 = g_srcs[s0 + k];
        hacc(acc, __ldg(base + i0 * 5 + c));
    }
    #pragma unroll
    for (int j = 0; j < 8; j++) acc[j] += b[j];
}

// hop 1: z1 = dinv^2 * gather(z0), fp16 out
__global__ void k_gather1() {
    int t = blockIdx.x * blockDim.x + threadIdx.x;
    if (t >= NROW * 5) return;
    int node = t / 5, c = t % 5;
    float acc[8];
    gather8(acc, node, c, g_z0);
    float d = g_dinv[node];
    float s = d * d;
    uint4 o;
    *(__half2*)&o.x = __floats2half2_rn(acc[0] * s, acc[1] * s);
    *(__half2*)&o.y = __floats2half2_rn(acc[2] * s, acc[3] * s);
    *(__half2*)&o.z = __floats2half2_rn(acc[4] * s, acc[5] * s);
    *(__half2*)&o.w = __floats2half2_rn(acc[6] * s, acc[7] * s);
    ((uint4*)g_z1)[t] = o;
}

// hop 2 fused with bias + log_softmax.
// Block: 320 threads = 64 rows x 5 chunks. smem staging, padded stride 41.
__global__ __launch_bounds__(320) void k_gather2_lsm(float* __restrict__ out,
                                                     const float* __restrict__ bias) {
    __shared__ float vals[64 * 41];
    __shared__ float lse[64];
    int t = threadIdx.x;
    int r = t / 5, c = t % 5;
    int node = blockIdx.x * 64 + r;
    bool active = (node < NROW);

    if (active) {
        float acc[8];
        gather8(acc, node, c, g_z1);
        float d = g_dinv[node];
        #pragma unroll
        for (int j = 0; j < 8; j++)
            vals[r * 41 + c * 8 + j] = acc[j] * d + __ldg(&bias[c * 8 + j]);
    }
    __syncthreads();

    if (t < 64 && blockIdx.x * 64 + t < NROW) {
        const float* v = vals + t * 41;
        float m = v[0];
        #pragma unroll
        for (int j = 1; j < OUT_CH; j++) m = fmaxf(m, v[j]);
        float s = 0.f;
        #pragma unroll
        for (int j = 0; j < OUT_CH; j++) s += expf(v[j] - m);
        lse[t] = m + logf(s);
    }
    __syncthreads();

    if (active) {
        float l = lse[r];
        float4 o0, o1;
        const float* v = vals + r * 41 + c * 8;
        o0.x = v[0] - l; o0.y = v[1] - l; o0.z = v[2] - l; o0.w = v[3] - l;
        o1.x = v[4] - l; o1.y = v[5] - l; o1.z = v[6] - l; o1.w = v[7] - l;
        float4* op = (float4*)(out + (size_t)node * OUT_CH + c * 8);
        op[0] = o0; op[1] = o1;
    }
}

// ---------------------------------------------------------------------------
extern "C" void kernel_launch(void* const* d_in, const int* in_sizes, int n_in,
                              void* d_out, int out_size) {
    const float* x  = (const float*)d_in[0];
    const int*   ei = (const int*)d_in[1];    // int32 (JAX default x64 disabled)
    const float* W  = (const float*)d_in[2];
    const float* b  = (const float*)d_in[3];
    float*       out = (float*)d_out;

    const int T = 256;
    const int gN  = (NROW + T - 1) / T;          // 391
    const int gE  = (NED + T - 1) / T;           // 12500
    const int gG  = (NROW * 5 + T - 1) / T;      // 1954
    const int gF  = (NROW + 63) / 64;            // 1563

    k_deg_init   <<<gN, T>>>();
    k_count      <<<gE, T>>>(ei);
    k_scan_nodes <<<NBLK, 256>>>();
    k_scan_tops  <<<1, 512>>>();
    k_finalize   <<<gN, T>>>();
    k_fill       <<<gE, T>>>(ei);
    k_gemm       <<<gN, T>>>(x, W);
    k_gather1    <<<gG, T>>>();
    k_gather2_lsm<<<gF, 320>>>(out, b);
}

// round 7
// speedup vs baseline: 2.9445x; 1.0746x over previous
#include <cuda_runtime.h>
#include <cuda_fp16.h>
#include <math.h>

#define NROW   100000
#define IN_CH  128
#define OUT_CH 40
#define NED    3200000
#define NBLK   ((NROW + 255) / 256)   // 391 scan blocks
#define GEMM_GRID ((NROW + 511) / 512)        // 196? no: 2 rows/thread, 256 thr -> 391
#define GGRID  ((NROW + 511) / 512 * 2)       // keep explicit below

// Scratch (static device globals)
__device__ __half2 g_z0[NROW * 20];  // (xW)*dinv, fp16, 80 B/row (8 MB)
__device__ __half2 g_z1[NROW * 20];  // after hop 1, fp16 (8 MB)
__device__ float   g_dinv[NROW];
__device__ int     g_degi[NROW];     // edge-only in-degree (self-loop folded later)
__device__ int     g_start[NROW];    // CSC row starts
__device__ int     g_cursor[NROW];
__device__ int     g_srcs[NED];      // CSC source indices (12.8 MB)
__device__ int     g_bsum[NBLK];
__device__ int     g_boff[NBLK];

// ---------------------------------------------------------------------------
// count in-degree, 4 edges per thread (int4)
__global__ void k_count(const int* __restrict__ ei) {
    int t = blockIdx.x * blockDim.x + threadIdx.x;
    if (t >= NED / 4) return;
    int4 c4 = __ldg((const int4*)(ei + NED) + t);
    int c;
    c = c4.x; if ((unsigned)c >= NROW) c = 0; atomicAdd(&g_degi[c], 1);
    c = c4.y; if ((unsigned)c >= NROW) c = 0; atomicAdd(&g_degi[c], 1);
    c = c4.z; if ((unsigned)c >= NROW) c = 0; atomicAdd(&g_degi[c], 1);
    c = c4.w; if ((unsigned)c >= NROW) c = 0; atomicAdd(&g_degi[c], 1);
}

// ---------------------------------------------------------------------------
// Two-level exclusive scan over edge counts
__global__ void k_scan_nodes() {
    __shared__ int sh[256];
    int tid = threadIdx.x;
    int i = blockIdx.x * 256 + tid;
    int c = (i < NROW) ? g_degi[i] : 0;
    sh[tid] = c;
    __syncthreads();
    #pragma unroll
    for (int off = 1; off < 256; off <<= 1) {
        int t = (tid >= off) ? sh[tid - off] : 0;
        __syncthreads();
        sh[tid] += t;
        __syncthreads();
    }
    if (i < NROW) g_start[i] = sh[tid] - c;
    if (tid == 255) g_bsum[blockIdx.x] = sh[tid];
}

__global__ void k_scan_tops() {
    __shared__ int sh[512];
    int tid = threadIdx.x;
    int v = (tid < NBLK) ? g_bsum[tid] : 0;
    sh[tid] = v;
    __syncthreads();
    #pragma unroll
    for (int off = 1; off < 512; off <<= 1) {
        int t = (tid >= off) ? sh[tid - off] : 0;
        __syncthreads();
        sh[tid] += t;
        __syncthreads();
    }
    if (tid < NBLK) g_boff[tid] = sh[tid] - v;
}

// finalize offsets + dinv = rsqrt(deg) with deg = edge_count + 1 (self-loop)
__global__ void k_finalize() {
    int i = blockIdx.x * blockDim.x + threadIdx.x;
    if (i >= NROW) return;
    int s = g_start[i] + g_boff[i >> 8];
    g_start[i] = s;
    g_cursor[i] = s;
    g_dinv[i] = rsqrtf((float)(g_degi[i] + 1));
}

// ---------------------------------------------------------------------------
// Fused kernel: blocks [0, NGEMM) do the GEMM (z0 = (xW)*dinv, fp16 out);
// blocks [NGEMM, NGEMM+NFILL) do the CSC fill (4 edges/thread).
// Independent work at the same dependency level -> overlapped in one launch.
#define NGEMM ((NROW / 2 + 255) / 256)        // 196 blocks? 2 rows/thread of 256 -> 391
#define NGEMM_BLOCKS ((NROW + 511) / 512)     // unused; explicit numbers below

__device__ __forceinline__ void fma4(float4& a, float s, float4 w) {
    a.x += s * w.x; a.y += s * w.y; a.z += s * w.z; a.w += s * w.w;
}

#define GEMM_BLOCKS 391                       // ceil(NROW / 256)  (thread = 2rows x 20ch)
#define FILL_BLOCKS 3125                      // NED / (256*4)

__global__ void k_fill_gemm(const float* __restrict__ x,
                            const float* __restrict__ W,
                            const int* __restrict__ ei) {
    __shared__ __align__(16) float wsm[IN_CH * OUT_CH];   // 20 KB (GEMM branch only)

    if (blockIdx.x < GEMM_BLOCKS) {
        // ---- GEMM branch ----
        for (int i = threadIdx.x; i < IN_CH * OUT_CH; i += blockDim.x)
            wsm[i] = W[i];
        __syncthreads();

        int gid = blockIdx.x * blockDim.x + threadIdx.x;
        if (gid >= NROW) return;
        int pair = gid >> 1;
        int ch   = (gid & 1) * 20;
        int r0 = pair * 2, r1 = r0 + 1;

        float4 acc0[5], acc1[5];
        #pragma unroll
        for (int j = 0; j < 5; j++) {
            acc0[j] = make_float4(0.f, 0.f, 0.f, 0.f);
            acc1[j] = make_float4(0.f, 0.f, 0.f, 0.f);
        }

        const float4* x0 = (const float4*)(x + (size_t)r0 * IN_CH);
        const float4* x1 = (const float4*)(x + (size_t)r1 * IN_CH);

        for (int k4 = 0; k4 < IN_CH / 4; k4++) {
            float4 xa = __ldg(&x0[k4]);
            float4 xb = __ldg(&x1[k4]);
            const float* wrow = wsm + (k4 * 4) * OUT_CH + ch;
            #pragma unroll
            for (int kk = 0; kk < 4; kk++) {
                float a = (&xa.x)[kk];
                float b = (&xb.x)[kk];
                const float4* wv = (const float4*)(wrow + kk * OUT_CH);
                #pragma unroll
                for (int j = 0; j < 5; j++) {
                    float4 w4 = wv[j];
                    fma4(acc0[j], a, w4);
                    fma4(acc1[j], b, w4);
                }
            }
        }

        float d0 = g_dinv[r0], d1 = g_dinv[r1];
        __half2* z0 = g_z0 + r0 * 20 + (ch >> 1);
        __half2* z1 = g_z0 + r1 * 20 + (ch >> 1);
        #pragma unroll
        for (int j = 0; j < 5; j++) {
            z0[2*j]   = __floats2half2_rn(acc0[j].x * d0, acc0[j].y * d0);
            z0[2*j+1] = __floats2half2_rn(acc0[j].z * d0, acc0[j].w * d0);
            z1[2*j]   = __floats2half2_rn(acc1[j].x * d1, acc1[j].y * d1);
            z1[2*j+1] = __floats2half2_rn(acc1[j].z * d1, acc1[j].w * d1);
        }
    } else {
        // ---- CSC fill branch: 4 edges per thread ----
        int t = (blockIdx.x - GEMM_BLOCKS) * blockDim.x + threadIdx.x;
        if (t >= NED / 4) return;
        int4 r4 = __ldg((const int4*)ei + t);
        int4 c4 = __ldg((const int4*)(ei + NED) + t);
        int r, c, slot;
        r = r4.x; c = c4.x;
        if ((unsigned)r >= NROW) r = 0;
        if ((unsigned)c >= NROW) c = 0;
        slot = atomicAdd(&g_cursor[c], 1); g_srcs[slot] = r;
        r = r4.y; c = c4.y;
        if ((unsigned)r >= NROW) r = 0;
        if ((unsigned)c >= NROW) c = 0;
        slot = atomicAdd(&g_cursor[c], 1); g_srcs[slot] = r;
        r = r4.z; c = c4.z;
        if ((unsigned)r >= NROW) r = 0;
        if ((unsigned)c >= NROW) c = 0;
        slot = atomicAdd(&g_cursor[c], 1); g_srcs[slot] = r;
        r = r4.w; c = c4.w;
        if ((unsigned)r >= NROW) r = 0;
        if ((unsigned)c >= NROW) c = 0;
        slot = atomicAdd(&g_cursor[c], 1); g_srcs[slot] = r;
    }
}

// ---------------------------------------------------------------------------
// fp16 gather core: thread = (node, chunk c in 0..4), chunk = 8 channels
// (one uint4 per gathered row). fp32 accumulators, 8-wide unroll.
__device__ __forceinline__ void hacc(float* a, uint4 v) {
    float2 f;
    f = __half22float2(*(__half2*)&v.x); a[0] += f.x; a[1] += f.y;
    f = __half22float2(*(__half2*)&v.y); a[2] += f.x; a[3] += f.y;
    f = __half22float2(*(__half2*)&v.z); a[4] += f.x; a[5] += f.y;
    f = __half22float2(*(__half2*)&v.w); a[6] += f.x; a[7] += f.y;
}

__device__ __forceinline__ void gather8(float* acc, int node, int c,
                                        const __half2* __restrict__ src) {
    const uint4* base = (const uint4*)src;     // 5 uint4 per row
    float b[8];
    #pragma unroll
    for (int j = 0; j < 8; j++) { acc[j] = 0.f; b[j] = 0.f; }

    uint4 self = __ldg(base + node * 5 + c);
    hacc(acc, self);

    int s0  = g_start[node];
    int cnt = g_degi[node];                    // edge-only count
    int k = 0;
    for (; k + 8 <= cnt; k += 8) {
        int i0 = g_srcs[s0 + k + 0];
        int i1 = g_srcs[s0 + k + 1];
        int i2 = g_srcs[s0 + k + 2];
        int i3 = g_srcs[s0 + k + 3];
        int i4 = g_srcs[s0 + k + 4];
        int i5 = g_srcs[s0 + k + 5];
        int i6 = g_srcs[s0 + k + 6];
        int i7 = g_srcs[s0 + k + 7];
        uint4 v0 = __ldg(base + i0 * 5 + c);
        uint4 v1 = __ldg(base + i1 * 5 + c);
        uint4 v2 = __ldg(base + i2 * 5 + c);
        uint4 v3 = __ldg(base + i3 * 5 + c);
        uint4 v4 = __ldg(base + i4 * 5 + c);
        uint4 v5 = __ldg(base + i5 * 5 + c);
        uint4 v6 = __ldg(base + i6 * 5 + c);
        uint4 v7 = __ldg(base + i7 * 5 + c);
        hacc(acc, v0); hacc(b, v1); hacc(acc, v2); hacc(b, v3);
        hacc(acc, v4); hacc(b, v5); hacc(acc, v6); hacc(b, v7);
    }
    for (; k < cnt; k++) {
        int i0 = g_srcs[s0 + k];
        hacc(acc, __ldg(base + i0 * 5 + c));
    }
    #pragma unroll
    for (int j = 0; j < 8; j++) acc[j] += b[j];
}

// hop 1: z1 = dinv^2 * gather(z0), fp16 out
__global__ void k_gather1() {
    int t = blockIdx.x * blockDim.x + threadIdx.x;
    if (t >= NROW * 5) return;
    int node = t / 5, c = t % 5;
    float acc[8];
    gather8(acc, node, c, g_z0);
    float d = g_dinv[node];
    float s = d * d;
    uint4 o;
    *(__half2*)&o.x = __floats2half2_rn(acc[0] * s, acc[1] * s);
    *(__half2*)&o.y = __floats2half2_rn(acc[2] * s, acc[3] * s);
    *(__half2*)&o.z = __floats2half2_rn(acc[4] * s, acc[5] * s);
    *(__half2*)&o.w = __floats2half2_rn(acc[6] * s, acc[7] * s);
    ((uint4*)g_z1)[t] = o;
}

// hop 2 fused with bias + log_softmax. Block: 320 threads = 64 rows x 5 chunks.
__global__ __launch_bounds__(320) void k_gather2_lsm(float* __restrict__ out,
                                                     const float* __restrict__ bias) {
    __shared__ float vals[64 * 41];
    __shared__ float lse[64];
    int t = threadIdx.x;
    int r = t / 5, c = t % 5;
    int node = blockIdx.x * 64 + r;
    bool active = (node < NROW);

    if (active) {
        float acc[8];
        gather8(acc, node, c, g_z1);
        float d = g_dinv[node];
        #pragma unroll
        for (int j = 0; j < 8; j++)
            vals[r * 41 + c * 8 + j] = acc[j] * d + __ldg(&bias[c * 8 + j]);
    }
    __syncthreads();

    if (t < 64 && blockIdx.x * 64 + t < NROW) {
        const float* v = vals + t * 41;
        float m = v[0];
        #pragma unroll
        for (int j = 1; j < OUT_CH; j++) m = fmaxf(m, v[j]);
        float s = 0.f;
        #pragma unroll
        for (int j = 0; j < OUT_CH; j++) s += expf(v[j] - m);
        lse[t] = m + logf(s);
    }
    __syncthreads();

    if (active) {
        float l = lse[r];
        float4 o0, o1;
        const float* v = vals + r * 41 + c * 8;
        o0.x = v[0] - l; o0.y = v[1] - l; o0.z = v[2] - l; o0.w = v[3] - l;
        o1.x = v[4] - l; o1.y = v[5] - l; o1.z = v[6] - l; o1.w = v[7] - l;
        float4* op = (float4*)(out + (size_t)node * OUT_CH + c * 8);
        op[0] = o0; op[1] = o1;
    }
}

// ---------------------------------------------------------------------------
extern "C" void kernel_launch(void* const* d_in, const int* in_sizes, int n_in,
                              void* d_out, int out_size) {
    const float* x  = (const float*)d_in[0];
    const int*   ei = (const int*)d_in[1];    // int32 (JAX default x64 disabled)
    const float* W  = (const float*)d_in[2];
    const float* b  = (const float*)d_in[3];
    float*       out = (float*)d_out;

    const int T = 256;
    const int gN  = (NROW + T - 1) / T;              // 391
    const int gC  = (NED / 4 + T - 1) / T;           // 3125
    const int gG  = (NROW * 5 + T - 1) / T;          // 1954
    const int gF  = (NROW + 63) / 64;                // 1563

    void* degi_ptr = nullptr;
    cudaGetSymbolAddress(&degi_ptr, g_degi);
    cudaMemsetAsync(degi_ptr, 0, NROW * sizeof(int), 0);

    k_count      <<<gC, T>>>(ei);
    k_scan_nodes <<<NBLK, 256>>>();
    k_scan_tops  <<<1, 512>>>();
    k_finalize   <<<gN, T>>>();
    k_fill_gemm  <<<GEMM_BLOCKS + FILL_BLOCKS, T>>>(x, W, ei);
    k_gather1    <<<gG, T>>>();
    k_gather2_lsm<<<gF, 320>>>(out, b);
}